// round 9
// baseline (speedup 1.0000x reference)
#include <cuda_runtime.h>

#define DIM 256
#define PLANE (DIM*DIM)
#define NELEM (DIM*DIM*DIM)

#define HTILES 64          // h tiles of 4 rows (1 row per thread)
#define DCHUNKS 9
#define DPC 29             // 9*29 = 261 >= 254; one clean wave at occ 4
#define NBLOCKS (HTILES*DCHUNKS)   // 576

__device__ float g_partials[NBLOCKS];
__device__ unsigned int g_count = 0;   // wraps to 0 each launch via atomicInc

__device__ __forceinline__ float sqrt_approx(float x) {
    float r;
    asm("sqrt.approx.f32 %0, %1;" : "=f"(r) : "f"(x));
    return r;
}

// packed f32x2 fma: r = a*b + c (elementwise on both halves)
__device__ __forceinline__ float2 fma2(float2 a, float2 b, float2 c) {
    float2 r;
    asm("fma.rn.f32x2 %0, %1, %2, %3;"
        : "=l"(reinterpret_cast<unsigned long long&>(r))
        : "l"(reinterpret_cast<unsigned long long&>(a)),
          "l"(reinterpret_cast<unsigned long long&>(b)),
          "l"(reinterpret_cast<unsigned long long&>(c)));
    return r;
}

__device__ __forceinline__ float2 lo2(float4 v) { return make_float2(v.x, v.y); }
__device__ __forceinline__ float2 hi2(float4 v) { return make_float2(v.z, v.w); }

__global__ __launch_bounds__(256, 4)
void grad_loss_fused(const float* __restrict__ x1,
                     const float* __restrict__ x2,
                     float* __restrict__ out) {
    __shared__ float ssum[8];
    __shared__ int s_last;

    const int tx = threadIdx.x;            // 0..63 -> w quad
    const int ty = threadIdx.y;            // 0..3  -> h row
    const int htile = blockIdx.x;          // 0..63
    const int chunk = blockIdx.y;          // 0..8
    const int bid = chunk * HTILES + htile;

    const int h  = 1 + htile * 4 + ty;     // 1..256
    const int w0 = tx * 4;
    const int d0 = 1 + chunk * DPC;
    const int niter = min(DIM - 2, d0 + DPC - 1) - d0 + 1;
    const int lane = tx & 31;

    const bool hcomp = (h <= DIM - 2);     // uniform per warp

    float local = 0.0f;

    if (hcomp) {
        const float wh  = (h == 1 || h == DIM - 2) ? 2.0f : 1.0f;
        const float wl  = (tx == 0)  ? 2.0f : 1.0f;
        const float wr  = (tx == 63) ? 2.0f : 1.0f;
        const bool  hasl = (tx > 0);
        const bool  hasr = (tx < 63);
        const bool  ld_lf = (lane == 0)  && hasl;   // warp-boundary edge loads
        const bool  ld_rt = (lane == 31) && hasr;

        const float2 neg1 = make_float2(-1.0f, -1.0f);
        const float2 eps2 = make_float2(1e-6f, 1e-6f);

        // q points at (d, h, w0); advance by PLANE per iteration.
        const float* q1 = x1 + d0 * PLANE + h * DIM + w0;
        const float* q2 = x2 + d0 * PLANE + h * DIM + w0;

        // Register window: A = d-1, B = d, C = d+1; D = d+2 prefetched.
        float4 A0 = *(const float4*)(q1 - PLANE);
        float4 A1 = *(const float4*)(q2 - PLANE);
        float4 B0 = *(const float4*)(q1);
        float4 B1 = *(const float4*)(q2);
        float4 C0 = *(const float4*)(q1 + PLANE);
        float4 C1 = *(const float4*)(q2 + PLANE);

        int d = d0;
        #pragma unroll 2
        for (int it = 0; it < niter; ++it, ++d, q1 += PLANE, q2 += PLANE) {
            // ---- prefetch plane d+2 (consumed NEXT iteration) ----
            const int pf = (d + 2 <= DIM - 1) ? 2 * PLANE : PLANE;
            const float4 D0 = *(const float4*)(q1 + pf);
            const float4 D1 = *(const float4*)(q2 + pf);

            // ---- cache-resident row-neighbor loads ----
            const float4 up0 = *(const float4*)(q1 - DIM);
            const float4 dn0 = *(const float4*)(q1 + DIM);
            const float4 up1 = *(const float4*)(q2 - DIM);
            const float4 dn1 = *(const float4*)(q2 + DIM);

            // ---- w-neighbors from registers via shfl; 1-lane edge loads ----
            float lf0 = __shfl_up_sync(0xffffffffu, B0.w, 1);
            float rt0 = __shfl_down_sync(0xffffffffu, B0.x, 1);
            float lf1 = __shfl_up_sync(0xffffffffu, B1.w, 1);
            float rt1 = __shfl_down_sync(0xffffffffu, B1.x, 1);
            if (ld_lf) { lf0 = q1[-1]; lf1 = q2[-1]; }
            if (ld_rt) { rt0 = q1[4];  rt1 = q2[4]; }

            const float wd = (d == 1 || d == DIM - 2) ? 2.0f : 1.0f;

            // ================= input 0 =================
            // packed h/d gradients: gh = dn - up, gd = C - A
            float2 gh01 = fma2(lo2(up0), neg1, lo2(dn0));
            float2 gh23 = fma2(hi2(up0), neg1, hi2(dn0));
            float2 gd01 = fma2(lo2(A0),  neg1, lo2(C0));
            float2 gd23 = fma2(hi2(A0),  neg1, hi2(C0));
            float2 t01  = fma2(gh01, gh01, eps2);
            float2 t23  = fma2(gh23, gh23, eps2);
            t01 = fma2(gd01, gd01, t01);
            t23 = fma2(gd23, gd23, t23);
            const float gw00 = B0.y - lf0;
            const float gw01 = B0.z - B0.x;
            const float gw02 = B0.w - B0.y;
            const float gw03 = rt0  - B0.z;
            const float m00 = sqrt_approx(fmaf(gw00, gw00, t01.x));
            const float m01 = sqrt_approx(fmaf(gw01, gw01, t01.y));
            const float m02 = sqrt_approx(fmaf(gw02, gw02, t23.x));
            const float m03 = sqrt_approx(fmaf(gw03, gw03, t23.y));

            // ================= input 1 =================
            gh01 = fma2(lo2(up1), neg1, lo2(dn1));
            gh23 = fma2(hi2(up1), neg1, hi2(dn1));
            gd01 = fma2(lo2(A1),  neg1, lo2(C1));
            gd23 = fma2(hi2(A1),  neg1, hi2(C1));
            t01  = fma2(gh01, gh01, eps2);
            t23  = fma2(gh23, gh23, eps2);
            t01 = fma2(gd01, gd01, t01);
            t23 = fma2(gd23, gd23, t23);
            const float gw10 = B1.y - lf1;
            const float gw11 = B1.z - B1.x;
            const float gw12 = B1.w - B1.y;
            const float gw13 = rt1  - B1.z;
            const float m10 = sqrt_approx(fmaf(gw10, gw10, t01.x));
            const float m11 = sqrt_approx(fmaf(gw11, gw11, t01.y));
            const float m12 = sqrt_approx(fmaf(gw12, gw12, t23.x));
            const float m13 = sqrt_approx(fmaf(gw13, gw13, t23.y));

            float s = 0.0f;
            if (hasl) s += fabsf(m00 - m10);
            s += wl * fabsf(m01 - m11);
            s += wr * fabsf(m02 - m12);
            if (hasr) s += fabsf(m03 - m13);
            local += wd * wh * s;

            // rotate window forward (renamed away by unroll)
            A0 = B0; A1 = B1; B0 = C0; B1 = C1; C0 = D0; C1 = D1;
        }
    }

    // ---- block reduction ----
    #pragma unroll
    for (int off = 16; off > 0; off >>= 1)
        local += __shfl_xor_sync(0xffffffffu, local, off);

    const int tid  = ty * 64 + tx;
    const int warp = tid >> 5;
    if (lane == 0) ssum[warp] = local;
    __syncthreads();

    if (tid == 0) {
        float v = 0.0f;
        #pragma unroll
        for (int i = 0; i < 8; ++i) v += ssum[i];
        g_partials[bid] = v;
        __threadfence();
        unsigned int t = atomicInc(&g_count, NBLOCKS - 1);
        s_last = (t == NBLOCKS - 1);
    }
    __syncthreads();

    // ---- last block finishes the global reduction ----
    if (s_last) {
        __threadfence();
        float s = 0.0f;
        const volatile float* gp = g_partials;
        for (int i = tid; i < NBLOCKS; i += 256)
            s += gp[i];
        #pragma unroll
        for (int off = 16; off > 0; off >>= 1)
            s += __shfl_xor_sync(0xffffffffu, s, off);
        if (lane == 0) ssum[warp] = s;
        __syncthreads();
        if (warp == 0) {
            float v = (lane < 8) ? ssum[lane] : 0.0f;
            #pragma unroll
            for (int off = 4; off > 0; off >>= 1)
                v += __shfl_xor_sync(0xffffffffu, v, off);
            if (lane == 0)
                out[0] = v * (1.0f / (float)NELEM);
        }
    }
}

extern "C" void kernel_launch(void* const* d_in, const int* in_sizes, int n_in,
                              void* d_out, int out_size) {
    const float* x1 = (const float*)d_in[0];
    const float* x2 = (const float*)d_in[1];
    float* out = (float*)d_out;
    (void)in_sizes; (void)n_in; (void)out_size;

    dim3 block(64, 4, 1);
    dim3 grid(HTILES, DCHUNKS, 1);
    grad_loss_fused<<<grid, block>>>(x1, x2, out);
}

// round 10
// speedup vs baseline: 1.2259x; 1.2259x over previous
#include <cuda_runtime.h>

#define DIM 256
#define PLANE (DIM*DIM)
#define NELEM (DIM*DIM*DIM)

#define HTILES 64          // h tiles of 4 rows (1 row per thread)
#define DCHUNKS 6
#define DPC 43             // 6*43 = 258 >= 254; one wave at occ 3 (384 <= 444)
#define NBLOCKS (HTILES*DCHUNKS)   // 384

__device__ float g_partials[NBLOCKS];
__device__ unsigned int g_count = 0;   // wraps to 0 each launch via atomicInc

__device__ __forceinline__ float sqrt_approx(float x) {
    float r;
    asm("sqrt.approx.f32 %0, %1;" : "=f"(r) : "f"(x));
    return r;
}

__global__ __launch_bounds__(256, 3)
void grad_loss_fused(const float* __restrict__ x1,
                     const float* __restrict__ x2,
                     float* __restrict__ out) {
    __shared__ float ssum[8];
    __shared__ int s_last;

    const int tx = threadIdx.x;            // 0..63 -> w quad
    const int ty = threadIdx.y;            // 0..3  -> h row
    const int htile = blockIdx.x;          // 0..63
    const int chunk = blockIdx.y;          // 0..5
    const int bid = chunk * HTILES + htile;

    const int h  = 1 + htile * 4 + ty;     // 1..256
    const int w0 = tx * 4;
    const int d0 = 1 + chunk * DPC;
    const int niter = min(DIM - 2, d0 + DPC - 1) - d0 + 1;  // 43 (last: 39)

    const bool hcomp = (h <= DIM - 2);     // uniform per warp

    float local = 0.0f;

    if (hcomp) {
        const float wh  = (h == 1 || h == DIM - 2) ? 2.0f : 1.0f;
        const float wl  = (tx == 0)  ? 2.0f : 1.0f;
        const float wr  = (tx == 63) ? 2.0f : 1.0f;
        const bool  hasl = (tx > 0);
        const bool  hasr = (tx < 63);

        // q points at (d, h, w0); advance by PLANE per iteration.
        const float* q1 = x1 + d0 * PLANE + h * DIM + w0;
        const float* q2 = x2 + d0 * PLANE + h * DIM + w0;

        // Carried state per input (all prefetch-distance >= 1):
        //   B  = center(plane d)      C  = center(plane d+1)
        //   U  = up-row(plane d)      Dn = down-row(plane d)
        // In-flight, issued at top of iter d: center(d+2), up/dn(plane d+1).
        // Only A(=center d-1, own L1 line from 2 iters ago) and the two edge
        // scalars are loaded in-iteration.
        float4 B0  = *(const float4*)(q1);
        float4 B1  = *(const float4*)(q2);
        float4 C0  = *(const float4*)(q1 + PLANE);
        float4 C1  = *(const float4*)(q2 + PLANE);
        float4 U0  = *(const float4*)(q1 - DIM);
        float4 U1  = *(const float4*)(q2 - DIM);
        float4 Dn0 = *(const float4*)(q1 + DIM);
        float4 Dn1 = *(const float4*)(q2 + DIM);

        int d = d0;
        #pragma unroll 2
        for (int it = 0; it < niter; ++it, ++d, q1 += PLANE, q2 += PLANE) {
            // ---- issue next-iteration loads FIRST (distance 1) ----
            const int pf = (d + 2 <= DIM - 1) ? 2 * PLANE : PLANE;
            const float4 Pn0  = *(const float4*)(q1 + pf);            // center d+2
            const float4 Pn1  = *(const float4*)(q2 + pf);
            const float4 Un0  = *(const float4*)(q1 + PLANE - DIM);   // up d+1
            const float4 Un1  = *(const float4*)(q2 + PLANE - DIM);
            const float4 Dnn0 = *(const float4*)(q1 + PLANE + DIM);   // dn d+1
            const float4 Dnn1 = *(const float4*)(q2 + PLANE + DIM);

            // ---- in-iteration L1-hit loads ----
            const float4 A0 = *(const float4*)(q1 - PLANE);
            const float4 A1 = *(const float4*)(q2 - PLANE);
            const float lf0 = hasl ? q1[-1] : 0.0f;
            const float rt0 = hasr ? q1[4]  : 0.0f;
            const float lf1 = hasl ? q2[-1] : 0.0f;
            const float rt1 = hasr ? q2[4]  : 0.0f;

            const float wd = (d == 1 || d == DIM - 2) ? 2.0f : 1.0f;

            float gw, gh, gd;
            float m00, m01, m02, m03;
            gw = B0.y - lf0;  gh = Dn0.x - U0.x;  gd = C0.x - A0.x;
            m00 = sqrt_approx(gw*gw + gh*gh + gd*gd + 1e-6f);
            gw = B0.z - B0.x; gh = Dn0.y - U0.y;  gd = C0.y - A0.y;
            m01 = sqrt_approx(gw*gw + gh*gh + gd*gd + 1e-6f);
            gw = B0.w - B0.y; gh = Dn0.z - U0.z;  gd = C0.z - A0.z;
            m02 = sqrt_approx(gw*gw + gh*gh + gd*gd + 1e-6f);
            gw = rt0 - B0.z;  gh = Dn0.w - U0.w;  gd = C0.w - A0.w;
            m03 = sqrt_approx(gw*gw + gh*gh + gd*gd + 1e-6f);

            float m10, m11, m12, m13;
            gw = B1.y - lf1;  gh = Dn1.x - U1.x;  gd = C1.x - A1.x;
            m10 = sqrt_approx(gw*gw + gh*gh + gd*gd + 1e-6f);
            gw = B1.z - B1.x; gh = Dn1.y - U1.y;  gd = C1.y - A1.y;
            m11 = sqrt_approx(gw*gw + gh*gh + gd*gd + 1e-6f);
            gw = B1.w - B1.y; gh = Dn1.z - U1.z;  gd = C1.z - A1.z;
            m12 = sqrt_approx(gw*gw + gh*gh + gd*gd + 1e-6f);
            gw = rt1 - B1.z;  gh = Dn1.w - U1.w;  gd = C1.w - A1.w;
            m13 = sqrt_approx(gw*gw + gh*gh + gd*gd + 1e-6f);

            float s = 0.0f;
            if (hasl) s += fabsf(m00 - m10);
            s += wl * fabsf(m01 - m11);
            s += wr * fabsf(m02 - m12);
            if (hasr) s += fabsf(m03 - m13);
            local += wd * wh * s;

            // rotate window forward (renamed away by unroll 2)
            B0 = C0;  B1 = C1;  C0 = Pn0;  C1 = Pn1;
            U0 = Un0; U1 = Un1; Dn0 = Dnn0; Dn1 = Dnn1;
        }
    }

    // ---- block reduction ----
    #pragma unroll
    for (int off = 16; off > 0; off >>= 1)
        local += __shfl_xor_sync(0xffffffffu, local, off);

    const int tid  = ty * 64 + tx;
    const int warp = tid >> 5;
    const int lane = tid & 31;
    if (lane == 0) ssum[warp] = local;
    __syncthreads();

    if (tid == 0) {
        float v = 0.0f;
        #pragma unroll
        for (int i = 0; i < 8; ++i) v += ssum[i];
        g_partials[bid] = v;
        __threadfence();
        unsigned int t = atomicInc(&g_count, NBLOCKS - 1);
        s_last = (t == NBLOCKS - 1);
    }
    __syncthreads();

    // ---- last block finishes the global reduction ----
    if (s_last) {
        __threadfence();
        float s = 0.0f;
        const volatile float* gp = g_partials;
        for (int i = tid; i < NBLOCKS; i += 256)
            s += gp[i];
        #pragma unroll
        for (int off = 16; off > 0; off >>= 1)
            s += __shfl_xor_sync(0xffffffffu, s, off);
        if (lane == 0) ssum[warp] = s;
        __syncthreads();
        if (warp == 0) {
            float v = (lane < 8) ? ssum[lane] : 0.0f;
            #pragma unroll
            for (int off = 4; off > 0; off >>= 1)
                v += __shfl_xor_sync(0xffffffffu, v, off);
            if (lane == 0)
                out[0] = v * (1.0f / (float)NELEM);
        }
    }
}

extern "C" void kernel_launch(void* const* d_in, const int* in_sizes, int n_in,
                              void* d_out, int out_size) {
    const float* x1 = (const float*)d_in[0];
    const float* x2 = (const float*)d_in[1];
    float* out = (float*)d_out;
    (void)in_sizes; (void)n_in; (void)out_size;

    dim3 block(64, 4, 1);
    dim3 grid(HTILES, DCHUNKS, 1);
    grad_loss_fused<<<grid, block>>>(x1, x2, out);
}